// round 8
// baseline (speedup 1.0000x reference)
#include <cuda_runtime.h>

#define B_ 2
#define S_ 4096
#define E_ 1024
#define H_ 16
#define D_ 64
#define W_ 256

// Scratch: q/k/v in [B,H,S,D] layout (33.5 MB each, static device arrays — no allocs)
__device__ float g_q[(size_t)B_ * H_ * S_ * D_];
__device__ float g_k[(size_t)B_ * H_ * S_ * D_];
__device__ float g_v[(size_t)B_ * H_ * S_ * D_];

// ---------------------------------------------------------------------------
// Kernel 1: fused QKV projection.  out = X @ W^T + b  (q additionally * 1/8)
// X: [M=8192, K=1024] row-major; W: [N=1024, K=1024] row-major (torch Linear).
// Output written in head-major [B,H,S,D] layout for the attention kernel.
// 128x128 tile, BK=8, 256 threads, 8x8 per thread.
// ---------------------------------------------------------------------------
__global__ __launch_bounds__(256, 2)
void qkv_gemm_kernel(const float* __restrict__ X,
                     const float* __restrict__ Wq, const float* __restrict__ bq,
                     const float* __restrict__ Wk, const float* __restrict__ bk,
                     const float* __restrict__ Wv, const float* __restrict__ bv)
{
    const float* Wt; const float* bias; float* outp; float scale;
    if (blockIdx.z == 0)      { Wt = Wq; bias = bq; outp = g_q; scale = 0.125f; }
    else if (blockIdx.z == 1) { Wt = Wk; bias = bk; outp = g_k; scale = 1.0f;   }
    else                      { Wt = Wv; bias = bv; outp = g_v; scale = 1.0f;   }

    __shared__ float As[8][128];   // [k][m] transposed
    __shared__ float Bs[8][128];   // [k][n] transposed

    const int m0  = blockIdx.x * 128;
    const int n0  = blockIdx.y * 128;
    const int tid = threadIdx.x;
    const int tx  = tid & 15;      // n direction
    const int ty  = tid >> 4;      // m direction

    const int lr = tid >> 1;          // 0..127 (row within tile)
    const int lc = (tid & 1) << 2;    // 0 or 4 (k offset of float4)

    const float* aptr = X  + (size_t)(m0 + lr) * E_ + lc;
    const float* bptr = Wt + (size_t)(n0 + lr) * E_ + lc;

    float acc[8][8];
    #pragma unroll
    for (int i = 0; i < 8; i++)
        #pragma unroll
        for (int j = 0; j < 8; j++) acc[i][j] = 0.f;

    for (int k0 = 0; k0 < E_; k0 += 8) {
        float4 a4 = *(const float4*)(aptr + k0);
        float4 b4 = *(const float4*)(bptr + k0);
        __syncthreads();
        As[lc + 0][lr] = a4.x; As[lc + 1][lr] = a4.y;
        As[lc + 2][lr] = a4.z; As[lc + 3][lr] = a4.w;
        Bs[lc + 0][lr] = b4.x; Bs[lc + 1][lr] = b4.y;
        Bs[lc + 2][lr] = b4.z; Bs[lc + 3][lr] = b4.w;
        __syncthreads();
        #pragma unroll
        for (int kk = 0; kk < 8; kk++) {
            float a[8], bb[8];
            *(float4*)&a[0]  = *(const float4*)&As[kk][ty * 8];
            *(float4*)&a[4]  = *(const float4*)&As[kk][ty * 8 + 4];
            *(float4*)&bb[0] = *(const float4*)&Bs[kk][tx * 8];
            *(float4*)&bb[4] = *(const float4*)&Bs[kk][tx * 8 + 4];
            #pragma unroll
            for (int i = 0; i < 8; i++)
                #pragma unroll
                for (int j = 0; j < 8; j++)
                    acc[i][j] = fmaf(a[i], bb[j], acc[i][j]);
        }
    }

    // Epilogue: bias, scale, scatter into [B,H,S,D]
    const int n = n0 + tx * 8;      // 8 consecutive n stay within one head (n%64 range)
    const int h = n >> 6;
    const int d = n & 63;
    float bias8[8];
    *(float4*)&bias8[0] = *(const float4*)&bias[n];
    *(float4*)&bias8[4] = *(const float4*)&bias[n + 4];

    #pragma unroll
    for (int i = 0; i < 8; i++) {
        int m   = m0 + ty * 8 + i;
        int bb_ = m >> 12;          // m / 4096
        int s   = m & (S_ - 1);
        float* orow = outp + (((size_t)bb_ * H_ + h) * S_ + s) * D_ + d;
        float4 o0, o1;
        o0.x = (acc[i][0] + bias8[0]) * scale; o0.y = (acc[i][1] + bias8[1]) * scale;
        o0.z = (acc[i][2] + bias8[2]) * scale; o0.w = (acc[i][3] + bias8[3]) * scale;
        o1.x = (acc[i][4] + bias8[4]) * scale; o1.y = (acc[i][5] + bias8[5]) * scale;
        o1.z = (acc[i][6] + bias8[6]) * scale; o1.w = (acc[i][7] + bias8[7]) * scale;
        *(float4*)orow       = o0;
        *(float4*)(orow + 4) = o1;
    }
}

// ---------------------------------------------------------------------------
// Kernel 2: banded attention with online softmax.
// Block = (64 queries) x (one head) x (one batch). 256 threads (16x16, 4x4 each).
// Key range per block: [q0-256, q0+63+256] -> 9 key tiles of 64.
// Smem: Qs [d][q] 16KB, KPs 16KB (K [d][k] during QK^T, then reused as P [q][k]),
// Vs [k][d] 16KB => exactly 48KB static.
// ---------------------------------------------------------------------------
__global__ __launch_bounds__(256, 2)
void banded_attn_kernel(const int* __restrict__ amask, float* __restrict__ out)
{
    __shared__ float Qs[64][64];    // [d][q]
    __shared__ float KPs[64][64];   // K as [d][k]; later P as [q][k]
    __shared__ float Vs[64][64];    // [k][d]

    const int q0 = blockIdx.x * 64;
    const int h  = blockIdx.y;
    const int b  = blockIdx.z;

    const int tid = threadIdx.x;
    const int tx  = tid & 15;       // key / d-column direction
    const int ty  = tid >> 4;       // query direction

    const size_t head_off = (((size_t)b * H_ + h) * S_) * D_;
    const float* qb_ = g_q + head_off;
    const float* kb_ = g_k + head_off;
    const float* vb_ = g_v + head_off;

    // Load Q tile transposed into Qs[d][q]
    #pragma unroll
    for (int it = 0; it < 4; it++) {
        int idx = tid + it * 256;
        int r   = idx >> 4;             // query row 0..63
        int d4  = (idx & 15) << 2;      // d offset
        float4 v = *(const float4*)(qb_ + (size_t)(q0 + r) * D_ + d4);
        Qs[d4 + 0][r] = v.x; Qs[d4 + 1][r] = v.y;
        Qs[d4 + 2][r] = v.z; Qs[d4 + 3][r] = v.w;
    }

    float m_run[4], l_run[4], oacc[4][4];
    #pragma unroll
    for (int i = 0; i < 4; i++) {
        m_run[i] = -1e30f; l_run[i] = 0.f;
        #pragma unroll
        for (int j = 0; j < 4; j++) oacc[i][j] = 0.f;
    }

    for (int t = 0; t < 9; t++) {
        const int kt0 = q0 - W_ + t * 64;
        if (kt0 + 63 < 0 || kt0 >= S_) continue;   // uniform across block

        __syncthreads();   // previous PV / Q preload ordered before tile overwrite

        // Load K tile (transposed) and V tile (natural); zero out-of-range rows
        #pragma unroll
        for (int it = 0; it < 4; it++) {
            int idx = tid + it * 256;
            int r   = idx >> 4;
            int d4  = (idx & 15) << 2;
            int jg  = kt0 + r;
            float4 kv = make_float4(0.f, 0.f, 0.f, 0.f);
            float4 vv = make_float4(0.f, 0.f, 0.f, 0.f);
            if (jg >= 0 && jg < S_) {
                kv = *(const float4*)(kb_ + (size_t)jg * D_ + d4);
                vv = *(const float4*)(vb_ + (size_t)jg * D_ + d4);
            }
            KPs[d4 + 0][r] = kv.x; KPs[d4 + 1][r] = kv.y;
            KPs[d4 + 2][r] = kv.z; KPs[d4 + 3][r] = kv.w;
            *(float4*)&Vs[r][d4] = vv;
        }
        __syncthreads();

        // S = Q K^T  (thread computes 4x4: queries ty*4+i, keys tx*4+j)
        float sc[4][4];
        #pragma unroll
        for (int i = 0; i < 4; i++)
            #pragma unroll
            for (int j = 0; j < 4; j++) sc[i][j] = 0.f;

        #pragma unroll 8
        for (int d = 0; d < 64; d++) {
            float qv[4], kv[4];
            *(float4*)&qv[0] = *(const float4*)&Qs[d][ty << 2];
            *(float4*)&kv[0] = *(const float4*)&KPs[d][tx << 2];
            #pragma unroll
            for (int i = 0; i < 4; i++)
                #pragma unroll
                for (int j = 0; j < 4; j++)
                    sc[i][j] = fmaf(qv[i], kv[j], sc[i][j]);
        }

        // Masking + online softmax (row stats replicated across the 16 tx lanes)
        float p[4][4];
        #pragma unroll
        for (int i = 0; i < 4; i++) {
            const int qi = q0 + (ty << 2) + i;
            float sv[4];
            float tmax = -1e30f;
            #pragma unroll
            for (int j = 0; j < 4; j++) {
                int jg  = kt0 + (tx << 2) + j;
                int dlt = jg - qi;
                bool valid = (jg >= 0) && (jg < S_) && (dlt >= -W_) && (dlt <= W_);
                float x = -1e30f;
                if (valid) {
                    x = sc[i][j];
                    if (amask[b * S_ + jg] != 0) x += -10000.f;
                }
                sv[j] = x;
                tmax = fmaxf(tmax, x);
            }
            // reduce over the 16 lanes sharing this row (xor 1,2,4,8 stays in half-warp)
            tmax = fmaxf(tmax, __shfl_xor_sync(0xffffffffu, tmax, 1, 32));
            tmax = fmaxf(tmax, __shfl_xor_sync(0xffffffffu, tmax, 2, 32));
            tmax = fmaxf(tmax, __shfl_xor_sync(0xffffffffu, tmax, 4, 32));
            tmax = fmaxf(tmax, __shfl_xor_sync(0xffffffffu, tmax, 8, 32));

            float mo   = m_run[i];
            float mn   = fmaxf(mo, tmax);
            float corr = __expf(mo - mn);
            float rs   = 0.f;
            #pragma unroll
            for (int j = 0; j < 4; j++) {
                float e = (sv[j] > -1e29f) ? __expf(sv[j] - mn) : 0.f;
                p[i][j] = e;
                rs += e;
            }
            rs += __shfl_xor_sync(0xffffffffu, rs, 1, 32);
            rs += __shfl_xor_sync(0xffffffffu, rs, 2, 32);
            rs += __shfl_xor_sync(0xffffffffu, rs, 4, 32);
            rs += __shfl_xor_sync(0xffffffffu, rs, 8, 32);

            l_run[i] = l_run[i] * corr + rs;
            m_run[i] = mn;
            #pragma unroll
            for (int j = 0; j < 4; j++) oacc[i][j] *= corr;
        }

        __syncthreads();   // all QK^T reads of KPs (as K) done before P overwrite
        #pragma unroll
        for (int i = 0; i < 4; i++)
            *(float4*)&KPs[(ty << 2) + i][tx << 2] =
                make_float4(p[i][0], p[i][1], p[i][2], p[i][3]);
        __syncthreads();

        // oacc += P @ V  (P rows broadcast across tx lanes; V float4 conflict-free)
        const float* pr0 = &KPs[(ty << 2) + 0][0];
        const float* pr1 = &KPs[(ty << 2) + 1][0];
        const float* pr2 = &KPs[(ty << 2) + 2][0];
        const float* pr3 = &KPs[(ty << 2) + 3][0];
        #pragma unroll 8
        for (int kk = 0; kk < 64; kk++) {
            float4 vv = *(const float4*)&Vs[kk][tx << 2];
            float p0 = pr0[kk], p1 = pr1[kk], p2 = pr2[kk], p3 = pr3[kk];
            oacc[0][0] = fmaf(p0, vv.x, oacc[0][0]); oacc[0][1] = fmaf(p0, vv.y, oacc[0][1]);
            oacc[0][2] = fmaf(p0, vv.z, oacc[0][2]); oacc[0][3] = fmaf(p0, vv.w, oacc[0][3]);
            oacc[1][0] = fmaf(p1, vv.x, oacc[1][0]); oacc[1][1] = fmaf(p1, vv.y, oacc[1][1]);
            oacc[1][2] = fmaf(p1, vv.z, oacc[1][2]); oacc[1][3] = fmaf(p1, vv.w, oacc[1][3]);
            oacc[2][0] = fmaf(p2, vv.x, oacc[2][0]); oacc[2][1] = fmaf(p2, vv.y, oacc[2][1]);
            oacc[2][2] = fmaf(p2, vv.z, oacc[2][2]); oacc[2][3] = fmaf(p2, vv.w, oacc[2][3]);
            oacc[3][0] = fmaf(p3, vv.x, oacc[3][0]); oacc[3][1] = fmaf(p3, vv.y, oacc[3][1]);
            oacc[3][2] = fmaf(p3, vv.z, oacc[3][2]); oacc[3][3] = fmaf(p3, vv.w, oacc[3][3]);
        }
    }

    // Normalize and write output [B,S,E] = [B,S,H*D]
    #pragma unroll
    for (int i = 0; i < 4; i++) {
        int si    = q0 + (ty << 2) + i;
        float inv = 1.f / l_run[i];
        float4 o;
        o.x = oacc[i][0] * inv; o.y = oacc[i][1] * inv;
        o.z = oacc[i][2] * inv; o.w = oacc[i][3] * inv;
        *(float4*)(out + ((size_t)b * S_ + si) * E_ + h * D_ + (tx << 2)) = o;
    }
}

// ---------------------------------------------------------------------------
extern "C" void kernel_launch(void* const* d_in, const int* in_sizes, int n_in,
                              void* d_out, int out_size)
{
    const float* hs    = (const float*)d_in[0];   // [B,S,E]
    const int*   amask = (const int*)  d_in[1];   // [B,S]
    const float* qw    = (const float*)d_in[2];
    const float* qb    = (const float*)d_in[3];
    const float* kw    = (const float*)d_in[4];
    const float* kb    = (const float*)d_in[5];
    const float* vw    = (const float*)d_in[6];
    const float* vb    = (const float*)d_in[7];
    float* out = (float*)d_out;

    dim3 g1((B_ * S_) / 128, E_ / 128, 3);   // 64 x 8 x 3
    qkv_gemm_kernel<<<g1, 256>>>(hs, qw, qb, kw, kb, vw, vb);

    dim3 g2(S_ / 64, H_, B_);                // 64 x 16 x 2
    banded_attn_kernel<<<g2, 256>>>(amask, out);
}

// round 9
// speedup vs baseline: 2.6219x; 2.6219x over previous
#include <cuda_runtime.h>
#include <cstdint>

#define B_ 2
#define S_ 4096
#define E_ 1024
#define H_ 16
#define D_ 64
#define W_ 256

// Scratch: q/k/v in [B,H,S,D] layout (static device arrays — no allocs)
__device__ float g_q[(size_t)B_ * H_ * S_ * D_];
__device__ float g_k[(size_t)B_ * H_ * S_ * D_];
__device__ float g_v[(size_t)B_ * H_ * S_ * D_];

// ---------------------------------------------------------------------------
// tf32 helpers
// ---------------------------------------------------------------------------
__device__ __forceinline__ uint32_t f2tf(float x) {
    uint32_t r;
    asm("cvt.rna.tf32.f32 %0, %1;" : "=r"(r) : "f"(x));
    return r;
}

__device__ __forceinline__ void mma8(float c[4],
                                     uint32_t a0, uint32_t a1, uint32_t a2, uint32_t a3,
                                     uint32_t b0, uint32_t b1) {
    asm volatile(
        "mma.sync.aligned.m16n8k8.row.col.f32.tf32.tf32.f32 "
        "{%0,%1,%2,%3}, {%4,%5,%6,%7}, {%8,%9}, {%0,%1,%2,%3};"
        : "+f"(c[0]), "+f"(c[1]), "+f"(c[2]), "+f"(c[3])
        : "r"(a0), "r"(a1), "r"(a2), "r"(a3), "r"(b0), "r"(b1));
}

// ---------------------------------------------------------------------------
// Kernel 1: fused QKV projection with tf32 tensor-core MMA.
// C[M=8192, N=1024] = X @ W^T + b  (q additionally * 1/8), scattered to [B,H,S,D].
// Block: 256 threads (8 warps), tile 128x128, BK=16.
// Warp w: (wm = w&1) * 64 rows x (wn = w>>1) * 32 cols; 4x4 grid of m16n8k8.
// Smem [k][m] tf32, row stride 136 -> conflict-free fragment loads.
// ---------------------------------------------------------------------------
__global__ __launch_bounds__(256)
void qkv_gemm_tf32(const float* __restrict__ X,
                   const float* __restrict__ Wq, const float* __restrict__ bq,
                   const float* __restrict__ Wk, const float* __restrict__ bk,
                   const float* __restrict__ Wv, const float* __restrict__ bv)
{
    const float* Wt; const float* bias; float* outp; float scale;
    if (blockIdx.z == 0)      { Wt = Wq; bias = bq; outp = g_q; scale = 0.125f; }
    else if (blockIdx.z == 1) { Wt = Wk; bias = bk; outp = g_k; scale = 1.0f;   }
    else                      { Wt = Wv; bias = bv; outp = g_v; scale = 1.0f;   }

    __shared__ uint32_t As[16][136];   // [k][m] tf32
    __shared__ uint32_t Bs[16][136];   // [k][n] tf32

    const int m0   = blockIdx.x * 128;
    const int n0   = blockIdx.y * 128;
    const int tid  = threadIdx.x;
    const int lane = tid & 31;
    const int wid  = tid >> 5;
    const int wm   = wid & 1;          // 0..1 -> 64-row band
    const int wn   = wid >> 1;         // 0..3 -> 32-col band
    const int lg   = lane >> 2;        // groupID 0..7
    const int lt   = lane & 3;         // thread-in-group 0..3

    // Gmem load mapping: thread covers rows rA and rA+64, k-chunk cA..cA+3
    const int rA = tid >> 2;           // 0..63
    const int cA = (tid & 3) << 2;     // 0,4,8,12

    const float* xp = X  + (size_t)(m0 + rA) * E_ + cA;
    const float* wp = Wt + (size_t)(n0 + rA) * E_ + cA;

    float c[4][4][4];
    #pragma unroll
    for (int i = 0; i < 4; i++)
        #pragma unroll
        for (int j = 0; j < 4; j++)
            #pragma unroll
            for (int r = 0; r < 4; r++) c[i][j][r] = 0.f;

    // Prefetch first K-tile
    float4 fx0 = *(const float4*)(xp);
    float4 fx1 = *(const float4*)(xp + (size_t)64 * E_);
    float4 fw0 = *(const float4*)(wp);
    float4 fw1 = *(const float4*)(wp + (size_t)64 * E_);

    for (int kt = 0; kt < 64; kt++) {
        __syncthreads();   // previous tile's fragment reads complete
        As[cA + 0][rA] = f2tf(fx0.x); As[cA + 1][rA] = f2tf(fx0.y);
        As[cA + 2][rA] = f2tf(fx0.z); As[cA + 3][rA] = f2tf(fx0.w);
        As[cA + 0][rA + 64] = f2tf(fx1.x); As[cA + 1][rA + 64] = f2tf(fx1.y);
        As[cA + 2][rA + 64] = f2tf(fx1.z); As[cA + 3][rA + 64] = f2tf(fx1.w);
        Bs[cA + 0][rA] = f2tf(fw0.x); Bs[cA + 1][rA] = f2tf(fw0.y);
        Bs[cA + 2][rA] = f2tf(fw0.z); Bs[cA + 3][rA] = f2tf(fw0.w);
        Bs[cA + 0][rA + 64] = f2tf(fw1.x); Bs[cA + 1][rA + 64] = f2tf(fw1.y);
        Bs[cA + 2][rA + 64] = f2tf(fw1.z); Bs[cA + 3][rA + 64] = f2tf(fw1.w);
        __syncthreads();

        // Prefetch next tile (overlaps with the MMA work below)
        if (kt < 63) {
            const int k0 = (kt + 1) * 16;
            fx0 = *(const float4*)(xp + k0);
            fx1 = *(const float4*)(xp + k0 + (size_t)64 * E_);
            fw0 = *(const float4*)(wp + k0);
            fw1 = *(const float4*)(wp + k0 + (size_t)64 * E_);
        }

        #pragma unroll
        for (int ks = 0; ks < 2; ks++) {
            const int k8 = ks * 8;
            uint32_t a[4][4], bf[4][2];
            #pragma unroll
            for (int mt = 0; mt < 4; mt++) {
                const int mrow = wm * 64 + mt * 16 + lg;
                a[mt][0] = As[k8 + lt][mrow];
                a[mt][1] = As[k8 + lt][mrow + 8];
                a[mt][2] = As[k8 + 4 + lt][mrow];
                a[mt][3] = As[k8 + 4 + lt][mrow + 8];
            }
            #pragma unroll
            for (int nt = 0; nt < 4; nt++) {
                const int ncol = wn * 32 + nt * 8 + lg;
                bf[nt][0] = Bs[k8 + lt][ncol];
                bf[nt][1] = Bs[k8 + 4 + lt][ncol];
            }
            #pragma unroll
            for (int mt = 0; mt < 4; mt++)
                #pragma unroll
                for (int nt = 0; nt < 4; nt++)
                    mma8(c[mt][nt], a[mt][0], a[mt][1], a[mt][2], a[mt][3],
                         bf[nt][0], bf[nt][1]);
        }
    }

    // Epilogue: bias + scale, scatter to [B,H,S,D]
    #pragma unroll
    for (int nt = 0; nt < 4; nt++) {
        const int n = n0 + wn * 32 + nt * 8 + (lt << 1);
        const int h = n >> 6;
        const int d = n & 63;
        const float b0v = bias[n], b1v = bias[n + 1];
        #pragma unroll
        for (int mt = 0; mt < 4; mt++) {
            #pragma unroll
            for (int half = 0; half < 2; half++) {
                const int m  = m0 + wm * 64 + mt * 16 + lg + half * 8;
                const int bb = m >> 12;
                const int s  = m & (S_ - 1);
                float2 o;
                o.x = (c[mt][nt][half * 2 + 0] + b0v) * scale;
                o.y = (c[mt][nt][half * 2 + 1] + b1v) * scale;
                *(float2*)(outp + (((size_t)bb * H_ + h) * S_ + s) * D_ + d) = o;
            }
        }
    }
}

// ---------------------------------------------------------------------------
// Kernel 2: banded attention with online softmax.
// Block = (64 queries) x (one head) x (one batch). 256 threads (16x16, 4x4 each).
// Key range per block: [q0-256, q0+63+256] -> 9 key tiles of 64.
// Smem: Qs [d][q] 16KB, KPs 16KB (K [d][k] during QK^T, then reused as P [q][k]),
// Vs [k][d] 16KB => exactly 48KB static.
// ---------------------------------------------------------------------------
__global__ __launch_bounds__(256, 2)
void banded_attn_kernel(const int* __restrict__ amask, float* __restrict__ out)
{
    __shared__ float Qs[64][64];    // [d][q]
    __shared__ float KPs[64][64];   // K as [d][k]; later P as [q][k]
    __shared__ float Vs[64][64];    // [k][d]

    const int q0 = blockIdx.x * 64;
    const int h  = blockIdx.y;
    const int b  = blockIdx.z;

    const int tid = threadIdx.x;
    const int tx  = tid & 15;       // key / d-column direction
    const int ty  = tid >> 4;       // query direction

    const size_t head_off = (((size_t)b * H_ + h) * S_) * D_;
    const float* qb_ = g_q + head_off;
    const float* kb_ = g_k + head_off;
    const float* vb_ = g_v + head_off;

    // Load Q tile transposed into Qs[d][q]
    #pragma unroll
    for (int it = 0; it < 4; it++) {
        int idx = tid + it * 256;
        int r   = idx >> 4;             // query row 0..63
        int d4  = (idx & 15) << 2;      // d offset
        float4 v = *(const float4*)(qb_ + (size_t)(q0 + r) * D_ + d4);
        Qs[d4 + 0][r] = v.x; Qs[d4 + 1][r] = v.y;
        Qs[d4 + 2][r] = v.z; Qs[d4 + 3][r] = v.w;
    }

    float m_run[4], l_run[4], oacc[4][4];
    #pragma unroll
    for (int i = 0; i < 4; i++) {
        m_run[i] = -1e30f; l_run[i] = 0.f;
        #pragma unroll
        for (int j = 0; j < 4; j++) oacc[i][j] = 0.f;
    }

    for (int t = 0; t < 9; t++) {
        const int kt0 = q0 - W_ + t * 64;
        if (kt0 + 63 < 0 || kt0 >= S_) continue;   // uniform across block

        __syncthreads();   // previous PV / Q preload ordered before tile overwrite

        // Load K tile (transposed) and V tile (natural); zero out-of-range rows
        #pragma unroll
        for (int it = 0; it < 4; it++) {
            int idx = tid + it * 256;
            int r   = idx >> 4;
            int d4  = (idx & 15) << 2;
            int jg  = kt0 + r;
            float4 kv = make_float4(0.f, 0.f, 0.f, 0.f);
            float4 vv = make_float4(0.f, 0.f, 0.f, 0.f);
            if (jg >= 0 && jg < S_) {
                kv = *(const float4*)(kb_ + (size_t)jg * D_ + d4);
                vv = *(const float4*)(vb_ + (size_t)jg * D_ + d4);
            }
            KPs[d4 + 0][r] = kv.x; KPs[d4 + 1][r] = kv.y;
            KPs[d4 + 2][r] = kv.z; KPs[d4 + 3][r] = kv.w;
            *(float4*)&Vs[r][d4] = vv;
        }
        __syncthreads();

        // Per-key additive mask (hoisted out of the i-loop: 4 global loads/tile)
        float am[4];
        #pragma unroll
        for (int j = 0; j < 4; j++) {
            int jg = kt0 + (tx << 2) + j;
            am[j] = (jg >= 0 && jg < S_ && amask[b * S_ + jg] != 0) ? -10000.f : 0.f;
        }

        // S = Q K^T  (thread computes 4x4: queries ty*4+i, keys tx*4+j)
        float sc[4][4];
        #pragma unroll
        for (int i = 0; i < 4; i++)
            #pragma unroll
            for (int j = 0; j < 4; j++) sc[i][j] = 0.f;

        #pragma unroll 8
        for (int d = 0; d < 64; d++) {
            float qv[4], kv[4];
            *(float4*)&qv[0] = *(const float4*)&Qs[d][ty << 2];
            *(float4*)&kv[0] = *(const float4*)&KPs[d][tx << 2];
            #pragma unroll
            for (int i = 0; i < 4; i++)
                #pragma unroll
                for (int j = 0; j < 4; j++)
                    sc[i][j] = fmaf(qv[i], kv[j], sc[i][j]);
        }

        // Masking + online softmax (row stats replicated across the 16 tx lanes)
        float p[4][4];
        #pragma unroll
        for (int i = 0; i < 4; i++) {
            const int qi = q0 + (ty << 2) + i;
            float sv[4];
            float tmax = -1e30f;
            #pragma unroll
            for (int j = 0; j < 4; j++) {
                int jg  = kt0 + (tx << 2) + j;
                int dlt = jg - qi;
                bool valid = (jg >= 0) && (jg < S_) && (dlt >= -W_) && (dlt <= W_);
                float x = valid ? (sc[i][j] + am[j]) : -1e30f;
                sv[j] = x;
                tmax = fmaxf(tmax, x);
            }
            tmax = fmaxf(tmax, __shfl_xor_sync(0xffffffffu, tmax, 1, 32));
            tmax = fmaxf(tmax, __shfl_xor_sync(0xffffffffu, tmax, 2, 32));
            tmax = fmaxf(tmax, __shfl_xor_sync(0xffffffffu, tmax, 4, 32));
            tmax = fmaxf(tmax, __shfl_xor_sync(0xffffffffu, tmax, 8, 32));

            float mo   = m_run[i];
            float mn   = fmaxf(mo, tmax);
            float corr = __expf(mo - mn);
            float rs   = 0.f;
            #pragma unroll
            for (int j = 0; j < 4; j++) {
                float e = (sv[j] > -1e29f) ? __expf(sv[j] - mn) : 0.f;
                p[i][j] = e;
                rs += e;
            }
            rs += __shfl_xor_sync(0xffffffffu, rs, 1, 32);
            rs += __shfl_xor_sync(0xffffffffu, rs, 2, 32);
            rs += __shfl_xor_sync(0xffffffffu, rs, 4, 32);
            rs += __shfl_xor_sync(0xffffffffu, rs, 8, 32);

            l_run[i] = l_run[i] * corr + rs;
            m_run[i] = mn;
            #pragma unroll
            for (int j = 0; j < 4; j++) oacc[i][j] *= corr;
        }

        __syncthreads();   // all QK^T reads of KPs (as K) done before P overwrite
        #pragma unroll
        for (int i = 0; i < 4; i++)
            *(float4*)&KPs[(ty << 2) + i][tx << 2] =
                make_float4(p[i][0], p[i][1], p[i][2], p[i][3]);
        __syncthreads();

        // oacc += P @ V  — all-float4 smem traffic (8 LDS.128 per 64 FMA)
        const int qrow = ty << 2;
        #pragma unroll 4
        for (int kk = 0; kk < 64; kk += 4) {
            float4 p0 = *(const float4*)&KPs[qrow + 0][kk];
            float4 p1 = *(const float4*)&KPs[qrow + 1][kk];
            float4 p2 = *(const float4*)&KPs[qrow + 2][kk];
            float4 p3 = *(const float4*)&KPs[qrow + 3][kk];
            float4 v0 = *(const float4*)&Vs[kk + 0][tx << 2];
            float4 v1 = *(const float4*)&Vs[kk + 1][tx << 2];
            float4 v2 = *(const float4*)&Vs[kk + 2][tx << 2];
            float4 v3 = *(const float4*)&Vs[kk + 3][tx << 2];

            #define PV_ROW(ii, pp)                                              \
                oacc[ii][0] = fmaf(pp.x, v0.x, oacc[ii][0]);                    \
                oacc[ii][1] = fmaf(pp.x, v0.y, oacc[ii][1]);                    \
                oacc[ii][2] = fmaf(pp.x, v0.z, oacc[ii][2]);                    \
                oacc[ii][3] = fmaf(pp.x, v0.w, oacc[ii][3]);                    \
                oacc[ii][0] = fmaf(pp.y, v1.x, oacc[ii][0]);                    \
                oacc[ii][1] = fmaf(pp.y, v1.y, oacc[ii][1]);                    \
                oacc[ii][2] = fmaf(pp.y, v1.z, oacc[ii][2]);                    \
                oacc[ii][3] = fmaf(pp.y, v1.w, oacc[ii][3]);                    \
                oacc[ii][0] = fmaf(pp.z, v2.x, oacc[ii][0]);                    \
                oacc[ii][1] = fmaf(pp.z, v2.y, oacc[ii][1]);                    \
                oacc[ii][2] = fmaf(pp.z, v2.z, oacc[ii][2]);                    \
                oacc[ii][3] = fmaf(pp.z, v2.w, oacc[ii][3]);                    \
                oacc[ii][0] = fmaf(pp.w, v3.x, oacc[ii][0]);                    \
                oacc[ii][1] = fmaf(pp.w, v3.y, oacc[ii][1]);                    \
                oacc[ii][2] = fmaf(pp.w, v3.z, oacc[ii][2]);                    \
                oacc[ii][3] = fmaf(pp.w, v3.w, oacc[ii][3]);
            PV_ROW(0, p0)
            PV_ROW(1, p1)
            PV_ROW(2, p2)
            PV_ROW(3, p3)
            #undef PV_ROW
        }
    }

    // Normalize and write output [B,S,E] = [B,S,H*D]
    #pragma unroll
    for (int i = 0; i < 4; i++) {
        int si    = q0 + (ty << 2) + i;
        float inv = 1.f / l_run[i];
        float4 o;
        o.x = oacc[i][0] * inv; o.y = oacc[i][1] * inv;
        o.z = oacc[i][2] * inv; o.w = oacc[i][3] * inv;
        *(float4*)(out + ((size_t)b * S_ + si) * E_ + h * D_ + (tx << 2)) = o;
    }
}

// ---------------------------------------------------------------------------
extern "C" void kernel_launch(void* const* d_in, const int* in_sizes, int n_in,
                              void* d_out, int out_size)
{
    const float* hs    = (const float*)d_in[0];   // [B,S,E]
    const int*   amask = (const int*)  d_in[1];   // [B,S]
    const float* qw    = (const float*)d_in[2];
    const float* qb    = (const float*)d_in[3];
    const float* kw    = (const float*)d_in[4];
    const float* kb    = (const float*)d_in[5];
    const float* vw    = (const float*)d_in[6];
    const float* vb    = (const float*)d_in[7];
    float* out = (float*)d_out;

    dim3 g1((B_ * S_) / 128, E_ / 128, 3);   // 64 x 8 x 3
    qkv_gemm_tf32<<<g1, 256>>>(hs, qw, qb, kw, kb, vw, vb);

    dim3 g2(S_ / 64, H_, B_);                // 64 x 16 x 2
    banded_attn_kernel<<<g2, 256>>>(amask, out);
}

// round 10
// speedup vs baseline: 4.1529x; 1.5839x over previous
#include <cuda_runtime.h>
#include <cstdint>

#define B_ 2
#define S_ 4096
#define E_ 1024
#define H_ 16
#define D_ 64
#define W_ 256

// Scratch: q/k/v in [B,H,S,D] layout (static device arrays — no allocs)
__device__ float g_q[(size_t)B_ * H_ * S_ * D_];
__device__ float g_k[(size_t)B_ * H_ * S_ * D_];
__device__ float g_v[(size_t)B_ * H_ * S_ * D_];

// ---------------------------------------------------------------------------
// tf32 helpers
// ---------------------------------------------------------------------------
__device__ __forceinline__ uint32_t f2tf(float x) {
    uint32_t r;
    asm("cvt.rna.tf32.f32 %0, %1;" : "=r"(r) : "f"(x));
    return r;
}

__device__ __forceinline__ void mma8(float c[4],
                                     uint32_t a0, uint32_t a1, uint32_t a2, uint32_t a3,
                                     uint32_t b0, uint32_t b1) {
    asm volatile(
        "mma.sync.aligned.m16n8k8.row.col.f32.tf32.tf32.f32 "
        "{%0,%1,%2,%3}, {%4,%5,%6,%7}, {%8,%9}, {%0,%1,%2,%3};"
        : "+f"(c[0]), "+f"(c[1]), "+f"(c[2]), "+f"(c[3])
        : "r"(a0), "r"(a1), "r"(a2), "r"(a3), "r"(b0), "r"(b1));
}

// ---------------------------------------------------------------------------
// Kernel 1: fused QKV projection with tf32 tensor-core MMA (unchanged from R8).
// ---------------------------------------------------------------------------
__global__ __launch_bounds__(256)
void qkv_gemm_tf32(const float* __restrict__ X,
                   const float* __restrict__ Wq, const float* __restrict__ bq,
                   const float* __restrict__ Wk, const float* __restrict__ bk,
                   const float* __restrict__ Wv, const float* __restrict__ bv)
{
    const float* Wt; const float* bias; float* outp; float scale;
    if (blockIdx.z == 0)      { Wt = Wq; bias = bq; outp = g_q; scale = 0.125f; }
    else if (blockIdx.z == 1) { Wt = Wk; bias = bk; outp = g_k; scale = 1.0f;   }
    else                      { Wt = Wv; bias = bv; outp = g_v; scale = 1.0f;   }

    __shared__ uint32_t As[16][136];   // [k][m] tf32
    __shared__ uint32_t Bs[16][136];   // [k][n] tf32

    const int m0   = blockIdx.x * 128;
    const int n0   = blockIdx.y * 128;
    const int tid  = threadIdx.x;
    const int lane = tid & 31;
    const int wid  = tid >> 5;
    const int wm   = wid & 1;
    const int wn   = wid >> 1;
    const int lg   = lane >> 2;
    const int lt   = lane & 3;

    const int rA = tid >> 2;
    const int cA = (tid & 3) << 2;

    const float* xp = X  + (size_t)(m0 + rA) * E_ + cA;
    const float* wp = Wt + (size_t)(n0 + rA) * E_ + cA;

    float c[4][4][4];
    #pragma unroll
    for (int i = 0; i < 4; i++)
        #pragma unroll
        for (int j = 0; j < 4; j++)
            #pragma unroll
            for (int r = 0; r < 4; r++) c[i][j][r] = 0.f;

    float4 fx0 = *(const float4*)(xp);
    float4 fx1 = *(const float4*)(xp + (size_t)64 * E_);
    float4 fw0 = *(const float4*)(wp);
    float4 fw1 = *(const float4*)(wp + (size_t)64 * E_);

    for (int kt = 0; kt < 64; kt++) {
        __syncthreads();
        As[cA + 0][rA] = f2tf(fx0.x); As[cA + 1][rA] = f2tf(fx0.y);
        As[cA + 2][rA] = f2tf(fx0.z); As[cA + 3][rA] = f2tf(fx0.w);
        As[cA + 0][rA + 64] = f2tf(fx1.x); As[cA + 1][rA + 64] = f2tf(fx1.y);
        As[cA + 2][rA + 64] = f2tf(fx1.z); As[cA + 3][rA + 64] = f2tf(fx1.w);
        Bs[cA + 0][rA] = f2tf(fw0.x); Bs[cA + 1][rA] = f2tf(fw0.y);
        Bs[cA + 2][rA] = f2tf(fw0.z); Bs[cA + 3][rA] = f2tf(fw0.w);
        Bs[cA + 0][rA + 64] = f2tf(fw1.x); Bs[cA + 1][rA + 64] = f2tf(fw1.y);
        Bs[cA + 2][rA + 64] = f2tf(fw1.z); Bs[cA + 3][rA + 64] = f2tf(fw1.w);
        __syncthreads();

        if (kt < 63) {
            const int k0 = (kt + 1) * 16;
            fx0 = *(const float4*)(xp + k0);
            fx1 = *(const float4*)(xp + k0 + (size_t)64 * E_);
            fw0 = *(const float4*)(wp + k0);
            fw1 = *(const float4*)(wp + k0 + (size_t)64 * E_);
        }

        #pragma unroll
        for (int ks = 0; ks < 2; ks++) {
            const int k8 = ks * 8;
            uint32_t a[4][4], bf[4][2];
            #pragma unroll
            for (int mt = 0; mt < 4; mt++) {
                const int mrow = wm * 64 + mt * 16 + lg;
                a[mt][0] = As[k8 + lt][mrow];
                a[mt][1] = As[k8 + lt][mrow + 8];
                a[mt][2] = As[k8 + 4 + lt][mrow];
                a[mt][3] = As[k8 + 4 + lt][mrow + 8];
            }
            #pragma unroll
            for (int nt = 0; nt < 4; nt++) {
                const int ncol = wn * 32 + nt * 8 + lg;
                bf[nt][0] = Bs[k8 + lt][ncol];
                bf[nt][1] = Bs[k8 + 4 + lt][ncol];
            }
            #pragma unroll
            for (int mt = 0; mt < 4; mt++)
                #pragma unroll
                for (int nt = 0; nt < 4; nt++)
                    mma8(c[mt][nt], a[mt][0], a[mt][1], a[mt][2], a[mt][3],
                         bf[nt][0], bf[nt][1]);
        }
    }

    #pragma unroll
    for (int nt = 0; nt < 4; nt++) {
        const int n = n0 + wn * 32 + nt * 8 + (lt << 1);
        const int h = n >> 6;
        const int d = n & 63;
        const float b0v = bias[n], b1v = bias[n + 1];
        #pragma unroll
        for (int mt = 0; mt < 4; mt++) {
            #pragma unroll
            for (int half = 0; half < 2; half++) {
                const int m  = m0 + wm * 64 + mt * 16 + lg + half * 8;
                const int bb = m >> 12;
                const int s  = m & (S_ - 1);
                float2 o;
                o.x = (c[mt][nt][half * 2 + 0] + b0v) * scale;
                o.y = (c[mt][nt][half * 2 + 1] + b1v) * scale;
                *(float2*)(outp + (((size_t)bb * H_ + h) * S_ + s) * D_ + d) = o;
            }
        }
    }
}

// ---------------------------------------------------------------------------
// Kernel 2: banded attention, tensor-core tf32 mma for QK^T and PV.
// Block = 64 queries x (one head) x (one batch). 128 threads = 4 warps.
// Warp w owns query rows [q0 + 16w, q0 + 16w + 15]; all 64 keys of each tile.
// 9 key tiles of 64 covering [q0-256, q0+319].
// Q fragments live in registers for the whole kernel (no Q smem).
// K natural [key][d] stride 68 (QK^T B-frag bank = 4*lg+lt, conflict-free).
// V natural [key][d] stride 72 (PV   B-frag bank = 8*lt+lg, conflict-free).
// P c-frag -> A-frag via 8 shfl + 4 sel per 8-key step (no P smem).
// ---------------------------------------------------------------------------
__global__ __launch_bounds__(128)
void banded_attn_tc(const int* __restrict__ amask, float* __restrict__ out)
{
    __shared__ uint32_t Ks[64][68];   // tf32, natural [key][d]
    __shared__ uint32_t Vs[64][72];   // tf32, natural [key][d]
    __shared__ float    am_s[64];     // additive mask per key of current tile

    const int q0 = blockIdx.x * 64;
    const int h  = blockIdx.y;
    const int b  = blockIdx.z;

    const int tid  = threadIdx.x;
    const int lane = tid & 31;
    const int wid  = tid >> 5;        // 0..3
    const int lg   = lane >> 2;       // 0..7
    const int lt   = lane & 3;        // 0..3

    const size_t head_off = (((size_t)b * H_ + h) * S_) * D_;
    const float* kb_ = g_k + head_off;
    const float* vb_ = g_v + head_off;

    // ---- persistent Q fragments (rows qi0 = q0+16w+lg, qi1 = qi0+8) ----
    const int qi0 = q0 + wid * 16 + lg;
    const int qi1 = qi0 + 8;
    const float* qr0 = g_q + head_off + (size_t)qi0 * D_;
    const float* qr1 = qr0 + 8 * D_;

    uint32_t qf[8][4];
    #pragma unroll
    for (int ks = 0; ks < 8; ks++) {
        qf[ks][0] = f2tf(qr0[ks * 8 + lt]);
        qf[ks][1] = f2tf(qr1[ks * 8 + lt]);
        qf[ks][2] = f2tf(qr0[ks * 8 + lt + 4]);
        qf[ks][3] = f2tf(qr1[ks * 8 + lt + 4]);
    }

    // valid key interval per row
    const int lo0 = max(0, qi0 - W_), hi0 = min(S_ - 1, qi0 + W_);
    const int lo1 = max(0, qi1 - W_), hi1 = min(S_ - 1, qi1 + W_);

    float m0r = -1e30f, m1r = -1e30f, l0 = 0.f, l1 = 0.f;
    float oacc[8][4];
    #pragma unroll
    for (int vn = 0; vn < 8; vn++)
        #pragma unroll
        for (int r = 0; r < 4; r++) oacc[vn][r] = 0.f;

    for (int t = 0; t < 9; t++) {
        const int kt0 = q0 - W_ + t * 64;
        if (kt0 + 63 < 0 || kt0 >= S_) continue;    // uniform across block

        __syncthreads();   // previous tile's smem reads complete

        // ---- load K,V tiles (tf32, natural layout), zero OOB rows ----
        #pragma unroll
        for (int it = 0; it < 8; it++) {
            int idx = tid + it * 128;       // 0..1023
            int r   = idx >> 4;             // key row 0..63
            int d4  = (idx & 15) << 2;      // d offset
            int jg  = kt0 + r;
            float4 kv = make_float4(0.f, 0.f, 0.f, 0.f);
            float4 vv = make_float4(0.f, 0.f, 0.f, 0.f);
            if (jg >= 0 && jg < S_) {
                kv = *(const float4*)(kb_ + (size_t)jg * D_ + d4);
                vv = *(const float4*)(vb_ + (size_t)jg * D_ + d4);
            }
            uint4 kt4, vt4;
            kt4.x = f2tf(kv.x); kt4.y = f2tf(kv.y); kt4.z = f2tf(kv.z); kt4.w = f2tf(kv.w);
            vt4.x = f2tf(vv.x); vt4.y = f2tf(vv.y); vt4.z = f2tf(vv.z); vt4.w = f2tf(vv.w);
            *(uint4*)&Ks[r][d4] = kt4;
            *(uint4*)&Vs[r][d4] = vt4;
        }
        if (tid < 64) {
            int jg = kt0 + tid;
            am_s[tid] = (jg >= 0 && jg < S_ && amask[b * S_ + jg] != 0) ? -10000.f : 0.f;
        }
        __syncthreads();

        // ---- S = Q K^T : 8 k-steps x 8 n-tiles of m16n8k8 ----
        float s[8][4];
        #pragma unroll
        for (int nt = 0; nt < 8; nt++)
            #pragma unroll
            for (int r = 0; r < 4; r++) s[nt][r] = 0.f;

        #pragma unroll
        for (int ks = 0; ks < 8; ks++) {
            const int k8 = ks * 8;
            #pragma unroll
            for (int nt = 0; nt < 8; nt++) {
                uint32_t b0 = Ks[nt * 8 + lg][k8 + lt];
                uint32_t b1 = Ks[nt * 8 + lg][k8 + lt + 4];
                mma8(s[nt], qf[ks][0], qf[ks][1], qf[ks][2], qf[ks][3], b0, b1);
            }
        }

        // ---- mask + online softmax (rows qi0, qi1; stats in-warp) ----
        float tmax0 = -1e30f, tmax1 = -1e30f;
        #pragma unroll
        for (int nt = 0; nt < 8; nt++) {
            const int c0  = (nt << 3) + (lt << 1);
            const int jg0 = kt0 + c0, jg1 = jg0 + 1;
            const float am0 = am_s[c0], am1 = am_s[c0 + 1];
            s[nt][0] = (jg0 >= lo0 && jg0 <= hi0) ? s[nt][0] + am0 : -1e30f;
            s[nt][1] = (jg1 >= lo0 && jg1 <= hi0) ? s[nt][1] + am1 : -1e30f;
            s[nt][2] = (jg0 >= lo1 && jg0 <= hi1) ? s[nt][2] + am0 : -1e30f;
            s[nt][3] = (jg1 >= lo1 && jg1 <= hi1) ? s[nt][3] + am1 : -1e30f;
            tmax0 = fmaxf(tmax0, fmaxf(s[nt][0], s[nt][1]));
            tmax1 = fmaxf(tmax1, fmaxf(s[nt][2], s[nt][3]));
        }
        tmax0 = fmaxf(tmax0, __shfl_xor_sync(0xffffffffu, tmax0, 1, 32));
        tmax0 = fmaxf(tmax0, __shfl_xor_sync(0xffffffffu, tmax0, 2, 32));
        tmax1 = fmaxf(tmax1, __shfl_xor_sync(0xffffffffu, tmax1, 1, 32));
        tmax1 = fmaxf(tmax1, __shfl_xor_sync(0xffffffffu, tmax1, 2, 32));

        const float mn0 = fmaxf(m0r, tmax0), mn1 = fmaxf(m1r, tmax1);
        const float corr0 = __expf(m0r - mn0), corr1 = __expf(m1r - mn1);

        float rs0 = 0.f, rs1 = 0.f;
        #pragma unroll
        for (int nt = 0; nt < 8; nt++) {
            float e0 = (s[nt][0] > -1e29f) ? __expf(s[nt][0] - mn0) : 0.f;
            float e1 = (s[nt][1] > -1e29f) ? __expf(s[nt][1] - mn0) : 0.f;
            float e2 = (s[nt][2] > -1e29f) ? __expf(s[nt][2] - mn1) : 0.f;
            float e3 = (s[nt][3] > -1e29f) ? __expf(s[nt][3] - mn1) : 0.f;
            s[nt][0] = e0; s[nt][1] = e1; s[nt][2] = e2; s[nt][3] = e3;
            rs0 += e0 + e1; rs1 += e2 + e3;
        }
        rs0 += __shfl_xor_sync(0xffffffffu, rs0, 1, 32);
        rs0 += __shfl_xor_sync(0xffffffffu, rs0, 2, 32);
        rs1 += __shfl_xor_sync(0xffffffffu, rs1, 1, 32);
        rs1 += __shfl_xor_sync(0xffffffffu, rs1, 2, 32);

        l0 = l0 * corr0 + rs0; m0r = mn0;
        l1 = l1 * corr1 + rs1; m1r = mn1;
        #pragma unroll
        for (int vn = 0; vn < 8; vn++) {
            oacc[vn][0] *= corr0; oacc[vn][1] *= corr0;
            oacc[vn][2] *= corr1; oacc[vn][3] *= corr1;
        }

        // ---- PV: permute P c-frag -> A-frag via shfl, then mma with V ----
        const int s0l = (lg << 2) + (lt >> 1);   // src lane for cols {lt}
        const int s1l = s0l + 2;                 // src lane for cols {lt+4}
        const bool odd = (lt & 1);
        #pragma unroll
        for (int kk = 0; kk < 8; kk++) {
            float t00 = __shfl_sync(0xffffffffu, s[kk][0], s0l, 32);
            float t01 = __shfl_sync(0xffffffffu, s[kk][1], s0l, 32);
            float t10 = __shfl_sync(0xffffffffu, s[kk][2], s0l, 32);
            float t11 = __shfl_sync(0xffffffffu, s[kk][3], s0l, 32);
            float t20 = __shfl_sync(0xffffffffu, s[kk][0], s1l, 32);
            float t21 = __shfl_sync(0xffffffffu, s[kk][1], s1l, 32);
            float t30 = __shfl_sync(0xffffffffu, s[kk][2], s1l, 32);
            float t31 = __shfl_sync(0xffffffffu, s[kk][3], s1l, 32);
            uint32_t a0 = f2tf(odd ? t01 : t00);
            uint32_t a1 = f2tf(odd ? t11 : t10);
            uint32_t a2 = f2tf(odd ? t21 : t20);
            uint32_t a3 = f2tf(odd ? t31 : t30);
            const int k8 = kk * 8;
            #pragma unroll
            for (int vn = 0; vn < 8; vn++) {
                uint32_t b0 = Vs[k8 + lt][vn * 8 + lg];
                uint32_t b1 = Vs[k8 + lt + 4][vn * 8 + lg];
                mma8(oacc[vn], a0, a1, a2, a3, b0, b1);
            }
        }
    }

    // ---- normalize + write out [B,S,E] ----
    const float inv0 = 1.f / l0, inv1 = 1.f / l1;
    float* o0 = out + ((size_t)b * S_ + qi0) * E_ + h * D_;
    float* o1 = out + ((size_t)b * S_ + qi1) * E_ + h * D_;
    #pragma unroll
    for (int vn = 0; vn < 8; vn++) {
        const int col = vn * 8 + (lt << 1);
        float2 r0, r1;
        r0.x = oacc[vn][0] * inv0; r0.y = oacc[vn][1] * inv0;
        r1.x = oacc[vn][2] * inv1; r1.y = oacc[vn][3] * inv1;
        *(float2*)(o0 + col) = r0;
        *(float2*)(o1 + col) = r1;
    }
}

// ---------------------------------------------------------------------------
extern "C" void kernel_launch(void* const* d_in, const int* in_sizes, int n_in,
                              void* d_out, int out_size)
{
    const float* hs    = (const float*)d_in[0];   // [B,S,E]
    const int*   amask = (const int*)  d_in[1];   // [B,S]
    const float* qw    = (const float*)d_in[2];
    const float* qb    = (const float*)d_in[3];
    const float* kw    = (const float*)d_in[4];
    const float* kb    = (const float*)d_in[5];
    const float* vw    = (const float*)d_in[6];
    const float* vb    = (const float*)d_in[7];
    float* out = (float*)d_out;

    dim3 g1((B_ * S_) / 128, E_ / 128, 3);   // 64 x 8 x 3
    qkv_gemm_tf32<<<g1, 256>>>(hs, qw, qb, kw, kb, vw, vb);

    dim3 g2(S_ / 64, H_, B_);                // 64 x 16 x 2
    banded_attn_tc<<<g2, 128>>>(amask, out);
}